// round 3
// baseline (speedup 1.0000x reference)
#include <cuda_runtime.h>
#include <cstdint>
#include <cstddef>

#define TOKENS   131072
#define CDIM     96
#define NWIN     512
#define NTOK     256
#define HD       24
#define NHEADS   4
#define HIDDEN_DIM 384

typedef unsigned long long ull;

// Scratch (device globals)
__device__ float g_qkv [(size_t)3 * TOKENS * CDIM];
__device__ float g_attn[(size_t)TOKENS * CDIM];
__device__ float g_x2  [(size_t)TOKENS * CDIM];
__device__ float g_h   [(size_t)TOKENS * HIDDEN_DIM];

__device__ __forceinline__ int nat_index(int t) {
    int r = t & 255, w = t >> 8;
    int b = w >> 8, wi = w & 255;
    int d  = ((((wi >> 6) & 3) << 2) | ((r >> 6) & 3));
    int hh = ((((wi >> 4) & 3) << 2) | ((r >> 4) & 3));
    int ww = ((((wi >> 2) & 3) << 2) | ((r >> 2) & 3));
    int tt = (((wi & 3) << 2) | (r & 3));
    d = (d + 2) & 15; hh = (hh + 2) & 15; ww = (ww + 2) & 15; tt = (tt + 2) & 15;
    return (((b * 16 + d) * 16 + hh) * 16 + ww) * 16 + tt;
}

__device__ __forceinline__ int group_of(int wi, int r) {
    int g = 0;
#pragma unroll
    for (int a = 3; a >= 0; --a) {
        int c = ((((wi >> (2 * a)) & 3) << 2) | ((r >> (2 * a)) & 3));
        int s = (c < 12) ? 0 : ((c < 14) ? 1 : 2);
        g = g * 3 + s;
    }
    return g;
}

// packed fp32x2 helpers (sm_103a)
__device__ __forceinline__ ull pk2(float a, float b) {
    ull r; asm("mov.b64 %0,{%1,%2};" : "=l"(r) : "f"(a), "f"(b)); return r;
}
__device__ __forceinline__ void fma2(ull& d, ull a, ull b) {
    asm("fma.rn.f32x2 %0,%1,%2,%0;" : "+l"(d) : "l"(a), "l"(b));
}
__device__ __forceinline__ void unpk2(float& a, float& b, ull v) {
    asm("mov.b64 {%0,%1},%2;" : "=f"(a), "=f"(b) : "l"(v));
}
__device__ __forceinline__ uint32_t to_tf32(float v) {
    uint32_t r; asm("cvt.rna.tf32.f32 %0,%1;" : "=r"(r) : "f"(v)); return r;
}

__device__ __forceinline__ void mma_tf32(float4& d, const uint32_t a[4], const uint32_t b[2]) {
    asm("mma.sync.aligned.m16n8k8.row.col.f32.tf32.tf32.f32 "
        "{%0,%1,%2,%3},{%4,%5,%6,%7},{%8,%9},{%0,%1,%2,%3};"
        : "+f"(d.x), "+f"(d.y), "+f"(d.z), "+f"(d.w)
        : "r"(a[0]), "r"(a[1]), "r"(a[2]), "r"(a[3]), "r"(b[0]), "r"(b[1]));
}

// ---------------------------------------------------------------------------
// tf32 tensor-core GEMM, full-K staging (chunks of 96):
//   C[M,N] = LN?(A)[M,K] @ W[N,K]^T  with fused epilogues.
// BM=128, BN=96, 256 threads (8 warps), warp tile 32x48.
// Smem rows padded to 100 -> bank (4*row+col)%32, conflict-free frags.
// ---------------------------------------------------------------------------
#define BMX 128
#define BNX 96
#define CHK 96
#define STR 100

enum { EPI_QKV = 0, EPI_PROJ = 1, EPI_FC1 = 2, EPI_FC2 = 3 };

template <int E, bool LNF, bool GATHER>
__global__ void __launch_bounds__(256, 2) gemm_tc2(const float* __restrict__ A, int K,
                                                   const float* __restrict__ W,
                                                   const float* __restrict__ bias,
                                                   const float* __restrict__ res,
                                                   const float* __restrict__ gamma,
                                                   const float* __restrict__ beta,
                                                   float* __restrict__ out) {
    extern __shared__ uint32_t sm4[];
    uint32_t (*As)[STR] = (uint32_t(*)[STR])sm4;
    uint32_t (*Ws)[STR] = (uint32_t(*)[STR])(sm4 + BMX * STR);

    const int tid  = threadIdx.x;
    const int warp = tid >> 5, lane = tid & 31;
    const int gid  = lane >> 2, tig = lane & 3;
    const int wm   = (warp >> 1) * 32;
    const int wn   = (warp & 1) * 48;
    const int m0   = blockIdx.x * BMX;
    const int nblk = blockIdx.y;
    const int n0   = nblk * BNX;

    float4 acc[2][6];
#pragma unroll
    for (int i = 0; i < 2; ++i)
#pragma unroll
        for (int j = 0; j < 6; ++j) acc[i][j] = make_float4(0.f, 0.f, 0.f, 0.f);

    for (int kc = 0; kc < K; kc += CHK) {
        if (kc) __syncthreads();
        // A tile: 128 x 96 -> 3072 float4, 12 per thread
#pragma unroll
        for (int it = 0; it < 12; ++it) {
            int idx = tid + it * 256;
            int row = idx / 24, c4 = (idx % 24) << 2;
            int m = m0 + row;
            const float* src = A + (size_t)(GATHER ? nat_index(m) : m) * K + kc + c4;
            float4 v = *(const float4*)src;
            if (LNF) {
                As[row][c4 + 0] = __float_as_uint(v.x); As[row][c4 + 1] = __float_as_uint(v.y);
                As[row][c4 + 2] = __float_as_uint(v.z); As[row][c4 + 3] = __float_as_uint(v.w);
            } else {
                As[row][c4 + 0] = to_tf32(v.x); As[row][c4 + 1] = to_tf32(v.y);
                As[row][c4 + 2] = to_tf32(v.z); As[row][c4 + 3] = to_tf32(v.w);
            }
        }
        // W tile: 96 x 96 -> 2304 float4, 9 per thread
#pragma unroll
        for (int it = 0; it < 9; ++it) {
            int idx = tid + it * 256;
            int row = idx / 24, c4 = (idx % 24) << 2;
            float4 v = *(const float4*)(W + (size_t)(n0 + row) * K + kc + c4);
            Ws[row][c4 + 0] = to_tf32(v.x); Ws[row][c4 + 1] = to_tf32(v.y);
            Ws[row][c4 + 2] = to_tf32(v.z); Ws[row][c4 + 3] = to_tf32(v.w);
        }
        __syncthreads();

        if (LNF) {  // K == 96: LayerNorm rows in-place, then tf32-ify
            int row = tid >> 1, half = tid & 1;
            float s = 0.f, sq = 0.f;
#pragma unroll
            for (int i = 0; i < 48; ++i) {
                float v = __uint_as_float(As[row][half * 48 + i]);
                s += v; sq += v * v;
            }
            s  += __shfl_xor_sync(0xffffffffu, s, 1);
            sq += __shfl_xor_sync(0xffffffffu, sq, 1);
            float mean = s * (1.f / 96.f);
            float var  = sq * (1.f / 96.f) - mean * mean;
            float rstd = rsqrtf(var + 1e-5f);
#pragma unroll
            for (int i = 0; i < 48; ++i) {
                int col = half * 48 + i;
                float v = __uint_as_float(As[row][col]);
                As[row][col] = to_tf32((v - mean) * rstd * gamma[col] + beta[col]);
            }
            __syncthreads();
        }

        // 12 uninterrupted mma k-steps
#pragma unroll
        for (int ks = 0; ks < 12; ++ks) {
            const int k = ks * 8;
            uint32_t a[2][4];
#pragma unroll
            for (int mi = 0; mi < 2; ++mi) {
                int r = wm + mi * 16 + gid;
                a[mi][0] = As[r][k + tig];
                a[mi][1] = As[r + 8][k + tig];
                a[mi][2] = As[r][k + tig + 4];
                a[mi][3] = As[r + 8][k + tig + 4];
            }
            uint32_t b[6][2];
#pragma unroll
            for (int ni = 0; ni < 6; ++ni) {
                int n = wn + ni * 8 + gid;
                b[ni][0] = Ws[n][k + tig];
                b[ni][1] = Ws[n][k + tig + 4];
            }
#pragma unroll
            for (int mi = 0; mi < 2; ++mi)
#pragma unroll
                for (int ni = 0; ni < 6; ++ni) mma_tf32(acc[mi][ni], a[mi], b[ni]);
        }
    }

    // ---- fused epilogues ----
#pragma unroll
    for (int mi = 0; mi < 2; ++mi) {
        int r0 = m0 + wm + mi * 16 + gid;
#pragma unroll
        for (int half = 0; half < 2; ++half) {
            int m = r0 + half * 8;
            size_t proj_dst = 0;
            if (E == EPI_PROJ) proj_dst = (size_t)nat_index(m) * CDIM;
            int w = m >> 8, rr = m & 255;
#pragma unroll
            for (int ni = 0; ni < 6; ++ni) {
                float v0 = half ? acc[mi][ni].z : acc[mi][ni].x;
                float v1 = half ? acc[mi][ni].w : acc[mi][ni].y;
#pragma unroll
                for (int e = 0; e < 2; ++e) {
                    int nl = wn + ni * 8 + tig * 2 + e;
                    float v = (e ? v1 : v0) + bias[n0 + nl];
                    if (E == EPI_QKV) {
                        const float scale = (nblk == 0) ? 0.20412414523193154f : 1.0f;
                        int h = nl / 24, dd = nl % 24;
                        out[(((size_t)nblk * NWIN + w) * NHEADS + h) * (NTOK * HD) + rr * HD + dd] = v * scale;
                    } else if (E == EPI_PROJ) {
                        out[proj_dst + nl] = res[proj_dst + nl] + v;
                    } else if (E == EPI_FC1) {
                        float gel = 0.5f * v * (1.f + erff(v * 0.70710678118654752f));
                        out[(size_t)m * HIDDEN_DIM + n0 + nl] = gel;
                    } else {
                        out[(size_t)m * CDIM + nl] = res[(size_t)m * CDIM + nl] + v;
                    }
                }
            }
        }
    }
}

// ---------------------------------------------------------------------------
// Attention: block per (window, head); thread = query row; packed fp32x2.
// ---------------------------------------------------------------------------
__global__ void __launch_bounds__(256) attn_kernel(const float* __restrict__ qkv,
                                                   float* __restrict__ attnout) {
    extern __shared__ float sm[];
    float* ks = sm;
    float* vs = sm + NTOK * HD;
    unsigned char* grp = (unsigned char*)(sm + 2 * NTOK * HD);

    const int w = blockIdx.x, h = blockIdx.y;
    const int tid = threadIdx.x;
    const size_t head_stride = (size_t)NTOK * HD;
    const float* kbase = qkv + (((size_t)1 * NWIN + w) * NHEADS + h) * head_stride;
    const float* vbase = qkv + (((size_t)2 * NWIN + w) * NHEADS + h) * head_stride;

#pragma unroll
    for (int it = 0; it < 6; ++it) {
        int idx = (tid + it * 256) * 4;
        *(float4*)(ks + idx) = *(const float4*)(kbase + idx);
        *(float4*)(vs + idx) = *(const float4*)(vbase + idx);
    }
    grp[tid] = (unsigned char)group_of(w & 255, tid);
    __syncthreads();

    const float* qrow = qkv + (((size_t)0 * NWIN + w) * NHEADS + h) * head_stride + tid * HD;
    ull q2[12];
#pragma unroll
    for (int i = 0; i < 12; ++i) {
        float2 v = *(const float2*)(qrow + 2 * i);
        q2[i] = pk2(v.x, v.y);
    }
    const int gi = grp[tid];

    ull o2[12];
#pragma unroll
    for (int i = 0; i < 12; ++i) o2[i] = 0ULL;
    float l = 0.f;

    const ull* ksm = (const ull*)ks;
    const ull* vsm = (const ull*)vs;

    for (int j = 0; j < NTOK; ++j) {
        const ull* k2 = ksm + j * 12;
        ull dp = 0ULL;
#pragma unroll
        for (int i = 0; i < 12; ++i) fma2(dp, q2[i], k2[i]);
        float slo, shi; unpk2(slo, shi, dp);
        float s = slo + shi;
        s = (grp[j] == gi) ? s : s - 100.f;
        float p = __expf(s);
        l += p;
        ull pp = pk2(p, p);
        const ull* v2 = vsm + j * 12;
#pragma unroll
        for (int i = 0; i < 12; ++i) fma2(o2[i], pp, v2[i]);
    }
    float inv = 1.f / l;
    float* op = attnout + ((size_t)w * NTOK + tid) * CDIM + h * HD;
#pragma unroll
    for (int i = 0; i < 12; ++i) {
        float a, b; unpk2(a, b, o2[i]);
        op[2 * i] = a * inv; op[2 * i + 1] = b * inv;
    }
}

// ---------------------------------------------------------------------------
extern "C" void kernel_launch(void* const* d_in, const int* in_sizes, int n_in,
                              void* d_out, int out_size) {
    (void)in_sizes; (void)n_in; (void)out_size;
    const float* x       = (const float*)d_in[0];
    const float* norm1_g = (const float*)d_in[2];
    const float* norm1_b = (const float*)d_in[3];
    const float* qkv_w   = (const float*)d_in[4];
    const float* qkv_b   = (const float*)d_in[5];
    const float* proj_w  = (const float*)d_in[6];
    const float* proj_b  = (const float*)d_in[7];
    const float* norm2_g = (const float*)d_in[8];
    const float* norm2_b = (const float*)d_in[9];
    const float* fc1_w   = (const float*)d_in[10];
    const float* fc1_b   = (const float*)d_in[11];
    const float* fc2_w   = (const float*)d_in[12];
    const float* fc2_b   = (const float*)d_in[13];
    float* out = (float*)d_out;

    float *qkv, *attn, *x2, *hbuf;
    cudaGetSymbolAddress((void**)&qkv,  g_qkv);
    cudaGetSymbolAddress((void**)&attn, g_attn);
    cudaGetSymbolAddress((void**)&x2,   g_x2);
    cudaGetSymbolAddress((void**)&hbuf, g_h);

    const int gsmem = (BMX + BNX) * STR * 4;  // 89600 B
    cudaFuncSetAttribute(gemm_tc2<EPI_QKV,  true,  true >, cudaFuncAttributeMaxDynamicSharedMemorySize, gsmem);
    cudaFuncSetAttribute(gemm_tc2<EPI_PROJ, false, false>, cudaFuncAttributeMaxDynamicSharedMemorySize, gsmem);
    cudaFuncSetAttribute(gemm_tc2<EPI_FC1,  true,  false>, cudaFuncAttributeMaxDynamicSharedMemorySize, gsmem);
    cudaFuncSetAttribute(gemm_tc2<EPI_FC2,  false, false>, cudaFuncAttributeMaxDynamicSharedMemorySize, gsmem);

    const int attn_smem = (2 * NTOK * HD) * 4 + 256;
    cudaFuncSetAttribute(attn_kernel, cudaFuncAttributeMaxDynamicSharedMemorySize, attn_smem);

    // 1) QKV projection with fused LN1 + shift + window partition (gather)
    gemm_tc2<EPI_QKV, true, true><<<dim3(TOKENS / BMX, 3), 256, gsmem>>>(
        x, CDIM, qkv_w, qkv_b, nullptr, norm1_g, norm1_b, qkv);
    // 2) windowed attention, analytic shift mask
    attn_kernel<<<dim3(NWIN, NHEADS), 256, attn_smem>>>(qkv, attn);
    // 3) proj + reverse partition/shift + residual -> x2 (natural order)
    gemm_tc2<EPI_PROJ, false, false><<<dim3(TOKENS / BMX, 1), 256, gsmem>>>(
        attn, CDIM, proj_w, proj_b, x, nullptr, nullptr, x2);
    // 4) fc1 with fused LN2 + exact GELU
    gemm_tc2<EPI_FC1, true, false><<<dim3(TOKENS / BMX, HIDDEN_DIM / BNX), 256, gsmem>>>(
        x2, CDIM, fc1_w, fc1_b, nullptr, norm2_g, norm2_b, hbuf);
    // 5) fc2 + residual -> output
    gemm_tc2<EPI_FC2, false, false><<<dim3(TOKENS / BMX, 1), 256, gsmem>>>(
        hbuf, HIDDEN_DIM, fc2_w, fc2_b, x2, nullptr, nullptr, out);
}

// round 4
// speedup vs baseline: 1.1895x; 1.1895x over previous
#include <cuda_runtime.h>
#include <cstdint>
#include <cstddef>

#define TOKENS   131072
#define CDIM     96
#define NWIN     512
#define NTOK     256
#define HD       24
#define NHEADS   4
#define HIDDEN_DIM 384

typedef unsigned long long ull;

// Scratch (device globals)
__device__ float g_xw  [(size_t)TOKENS * CDIM];
__device__ float g_qkv [(size_t)3 * TOKENS * CDIM];
__device__ float g_attn[(size_t)TOKENS * CDIM];
__device__ float g_x2  [(size_t)TOKENS * CDIM];
__device__ float g_xn2 [(size_t)TOKENS * CDIM];
__device__ float g_h   [(size_t)TOKENS * HIDDEN_DIM];

__device__ __forceinline__ int nat_index(int t) {
    int r = t & 255, w = t >> 8;
    int b = w >> 8, wi = w & 255;
    int d  = ((((wi >> 6) & 3) << 2) | ((r >> 6) & 3));
    int hh = ((((wi >> 4) & 3) << 2) | ((r >> 4) & 3));
    int ww = ((((wi >> 2) & 3) << 2) | ((r >> 2) & 3));
    int tt = (((wi & 3) << 2) | (r & 3));
    d = (d + 2) & 15; hh = (hh + 2) & 15; ww = (ww + 2) & 15; tt = (tt + 2) & 15;
    return (((b * 16 + d) * 16 + hh) * 16 + ww) * 16 + tt;
}

__device__ __forceinline__ int group_of(int wi, int r) {
    int g = 0;
#pragma unroll
    for (int a = 3; a >= 0; --a) {
        int c = ((((wi >> (2 * a)) & 3) << 2) | ((r >> (2 * a)) & 3));
        int s = (c < 12) ? 0 : ((c < 14) ? 1 : 2);
        g = g * 3 + s;
    }
    return g;
}

// packed fp32x2 helpers (sm_103a)
__device__ __forceinline__ ull pk2(float a, float b) {
    ull r; asm("mov.b64 %0,{%1,%2};" : "=l"(r) : "f"(a), "f"(b)); return r;
}
__device__ __forceinline__ void fma2(ull& d, ull a, ull b) {
    asm("fma.rn.f32x2 %0,%1,%2,%0;" : "+l"(d) : "l"(a), "l"(b));
}
__device__ __forceinline__ void unpk2(float& a, float& b, ull v) {
    asm("mov.b64 {%0,%1},%2;" : "=f"(a), "=f"(b) : "l"(v));
}

__device__ __forceinline__ void mma_tf32(float4& d, const uint32_t a[4], const uint32_t b[2]) {
    asm("mma.sync.aligned.m16n8k8.row.col.f32.tf32.tf32.f32 "
        "{%0,%1,%2,%3},{%4,%5,%6,%7},{%8,%9},{%0,%1,%2,%3};"
        : "+f"(d.x), "+f"(d.y), "+f"(d.z), "+f"(d.w)
        : "r"(a[0]), "r"(a[1]), "r"(a[2]), "r"(a[3]), "r"(b[0]), "r"(b[1]));
}

// cp.async helpers
__device__ __forceinline__ void cp16(uint32_t dst, const void* src) {
    asm volatile("cp.async.cg.shared.global [%0],[%1],16;" :: "r"(dst), "l"(src));
}
__device__ __forceinline__ void cp_commit() { asm volatile("cp.async.commit_group;"); }
template <int N>
__device__ __forceinline__ void cp_wait() { asm volatile("cp.async.wait_group %0;" :: "n"(N)); }

// ---------------------------------------------------------------------------
// LayerNorm (warp per token); gather=1 fuses shift+window partition.
// ---------------------------------------------------------------------------
__global__ void ln_kernel(const float* __restrict__ x,
                          const float* __restrict__ gamma,
                          const float* __restrict__ beta,
                          float* __restrict__ out, int gather) {
    int t = blockIdx.x * 8 + (threadIdx.x >> 5);
    int lane = threadIdx.x & 31;
    int src = gather ? nat_index(t) : t;
    const float* row = x + (size_t)src * CDIM;
    float v0 = row[lane], v1 = row[lane + 32], v2 = row[lane + 64];
    float s = v0 + v1 + v2;
    float sq = v0 * v0 + v1 * v1 + v2 * v2;
#pragma unroll
    for (int o = 16; o; o >>= 1) {
        s  += __shfl_xor_sync(0xffffffffu, s, o);
        sq += __shfl_xor_sync(0xffffffffu, sq, o);
    }
    float mean = s * (1.f / 96.f);
    float var = sq * (1.f / 96.f) - mean * mean;
    float rstd = rsqrtf(var + 1e-5f);
    float* op = out + (size_t)t * CDIM;
    op[lane]      = (v0 - mean) * rstd * gamma[lane]      + beta[lane];
    op[lane + 32] = (v1 - mean) * rstd * gamma[lane + 32] + beta[lane + 32];
    op[lane + 64] = (v2 - mean) * rstd * gamma[lane + 64] + beta[lane + 64];
}

// ---------------------------------------------------------------------------
// tf32 tensor-core GEMM, cp.async double-buffered, BK=32.
// C[M,N] = A[M,K] @ W[N,K]^T. fp32 bits fed to HMMA.TF32 (hw truncates).
// BM=128, BN=96, 256 threads (8 warps), warp tile 32x48, stride-36 smem.
// ---------------------------------------------------------------------------
#define BMX 128
#define BNX 96
#define BKX 32
#define STR 36

enum { EPI_QKV = 0, EPI_PROJ = 1, EPI_FC1 = 2, EPI_FC2 = 3 };

template <int E>
__global__ void __launch_bounds__(256) gemm_pipe(const float* __restrict__ A, int K,
                                                 const float* __restrict__ W,
                                                 const float* __restrict__ bias,
                                                 const float* __restrict__ res,
                                                 float* __restrict__ out) {
    extern __shared__ float smem[];
    // [stage][A: 128*36][W: 96*36]
    const int ASZ = BMX * STR, WSZ = BNX * STR, STG = ASZ + WSZ;

    const int tid  = threadIdx.x;
    const int warp = tid >> 5, lane = tid & 31;
    const int gid  = lane >> 2, tig = lane & 3;
    const int wm   = (warp >> 1) * 32;
    const int wn   = (warp & 1) * 48;
    const int m0   = blockIdx.x * BMX;
    const int nblk = blockIdx.y;
    const int n0   = nblk * BNX;

    uint32_t smem_u = (uint32_t)__cvta_generic_to_shared(smem);

    // per-thread copy slots
    const int arow = tid >> 3, ac4 = (tid & 7) << 2;         // +64 rows x2 more
    const int wrow = tid >> 3, wc4 = (tid & 7) << 2;

    const float* Abase = A + (size_t)m0 * K;
    const float* Wbase = W + (size_t)n0 * K;

    auto load_stage = [&](int s, int kc) {
        uint32_t abuf = smem_u + (s * STG) * 4;
        uint32_t wbuf = smem_u + (s * STG + ASZ) * 4;
#pragma unroll
        for (int it = 0; it < 4; ++it) {
            int row = arow + it * 32;
            cp16(abuf + (row * STR + ac4) * 4, Abase + (size_t)row * K + kc + ac4);
        }
#pragma unroll
        for (int it = 0; it < 3; ++it) {
            int row = wrow + it * 32;
            cp16(wbuf + (row * STR + wc4) * 4, Wbase + (size_t)row * K + kc + wc4);
        }
    };

    float4 acc[2][6];
#pragma unroll
    for (int i = 0; i < 2; ++i)
#pragma unroll
        for (int j = 0; j < 6; ++j) acc[i][j] = make_float4(0.f, 0.f, 0.f, 0.f);

    const int nc = K / BKX;
    load_stage(0, 0);
    cp_commit();

    for (int c = 0; c < nc; ++c) {
        if (c + 1 < nc) {
            load_stage((c + 1) & 1, (c + 1) * BKX);
            cp_commit();
            cp_wait<1>();
        } else {
            cp_wait<0>();
        }
        __syncthreads();

        const uint32_t* As = (const uint32_t*)(smem + (c & 1) * STG);
        const uint32_t* Ws = (const uint32_t*)(smem + (c & 1) * STG + ASZ);
#pragma unroll
        for (int ks = 0; ks < 4; ++ks) {
            const int k = ks * 8;
            uint32_t a[2][4];
#pragma unroll
            for (int mi = 0; mi < 2; ++mi) {
                int r = wm + mi * 16 + gid;
                a[mi][0] = As[r * STR + k + tig];
                a[mi][1] = As[(r + 8) * STR + k + tig];
                a[mi][2] = As[r * STR + k + tig + 4];
                a[mi][3] = As[(r + 8) * STR + k + tig + 4];
            }
            uint32_t b[6][2];
#pragma unroll
            for (int ni = 0; ni < 6; ++ni) {
                int n = wn + ni * 8 + gid;
                b[ni][0] = Ws[n * STR + k + tig];
                b[ni][1] = Ws[n * STR + k + tig + 4];
            }
#pragma unroll
            for (int mi = 0; mi < 2; ++mi)
#pragma unroll
                for (int ni = 0; ni < 6; ++ni) mma_tf32(acc[mi][ni], a[mi], b[ni]);
        }
        __syncthreads();
    }

    // ---- fused epilogues ----
#pragma unroll
    for (int mi = 0; mi < 2; ++mi) {
        int r0 = m0 + wm + mi * 16 + gid;
#pragma unroll
        for (int half = 0; half < 2; ++half) {
            int m = r0 + half * 8;
            size_t proj_dst = 0;
            if (E == EPI_PROJ) proj_dst = (size_t)nat_index(m) * CDIM;
            int w = m >> 8, rr = m & 255;
#pragma unroll
            for (int ni = 0; ni < 6; ++ni) {
                float v0 = half ? acc[mi][ni].z : acc[mi][ni].x;
                float v1 = half ? acc[mi][ni].w : acc[mi][ni].y;
#pragma unroll
                for (int e = 0; e < 2; ++e) {
                    int nl = wn + ni * 8 + tig * 2 + e;
                    float v = (e ? v1 : v0) + bias[n0 + nl];
                    if (E == EPI_QKV) {
                        const float scale = (nblk == 0) ? 0.20412414523193154f : 1.0f;
                        int h = nl / 24, dd = nl % 24;
                        out[(((size_t)nblk * NWIN + w) * NHEADS + h) * (NTOK * HD) + rr * HD + dd] = v * scale;
                    } else if (E == EPI_PROJ) {
                        out[proj_dst + nl] = res[proj_dst + nl] + v;
                    } else if (E == EPI_FC1) {
                        float gel = 0.5f * v * (1.f + erff(v * 0.70710678118654752f));
                        out[(size_t)m * HIDDEN_DIM + n0 + nl] = gel;
                    } else {
                        out[(size_t)m * CDIM + nl] = res[(size_t)m * CDIM + nl] + v;
                    }
                }
            }
        }
    }
}

// ---------------------------------------------------------------------------
// Attention: block per (window, head); thread = query row; packed fp32x2.
// ---------------------------------------------------------------------------
__global__ void __launch_bounds__(256) attn_kernel(const float* __restrict__ qkv,
                                                   float* __restrict__ attnout) {
    extern __shared__ float sm[];
    float* ks = sm;
    float* vs = sm + NTOK * HD;
    unsigned char* grp = (unsigned char*)(sm + 2 * NTOK * HD);

    const int w = blockIdx.x, h = blockIdx.y;
    const int tid = threadIdx.x;
    const size_t head_stride = (size_t)NTOK * HD;
    const float* kbase = qkv + (((size_t)1 * NWIN + w) * NHEADS + h) * head_stride;
    const float* vbase = qkv + (((size_t)2 * NWIN + w) * NHEADS + h) * head_stride;

#pragma unroll
    for (int it = 0; it < 6; ++it) {
        int idx = (tid + it * 256) * 4;
        *(float4*)(ks + idx) = *(const float4*)(kbase + idx);
        *(float4*)(vs + idx) = *(const float4*)(vbase + idx);
    }
    grp[tid] = (unsigned char)group_of(w & 255, tid);
    __syncthreads();

    const float* qrow = qkv + (((size_t)0 * NWIN + w) * NHEADS + h) * head_stride + tid * HD;
    ull q2[12];
#pragma unroll
    for (int i = 0; i < 12; ++i) {
        float2 v = *(const float2*)(qrow + 2 * i);
        q2[i] = pk2(v.x, v.y);
    }
    const int gi = grp[tid];

    ull o2[12];
#pragma unroll
    for (int i = 0; i < 12; ++i) o2[i] = 0ULL;
    float l = 0.f;

    const ull* ksm = (const ull*)ks;
    const ull* vsm = (const ull*)vs;

    for (int j = 0; j < NTOK; ++j) {
        const ull* k2 = ksm + j * 12;
        ull dp = 0ULL;
#pragma unroll
        for (int i = 0; i < 12; ++i) fma2(dp, q2[i], k2[i]);
        float slo, shi; unpk2(slo, shi, dp);
        float s = slo + shi;
        s = (grp[j] == gi) ? s : s - 100.f;
        float p = __expf(s);
        l += p;
        ull pp = pk2(p, p);
        const ull* v2 = vsm + j * 12;
#pragma unroll
        for (int i = 0; i < 12; ++i) fma2(o2[i], pp, v2[i]);
    }
    float inv = 1.f / l;
    float* op = attnout + ((size_t)w * NTOK + tid) * CDIM + h * HD;
#pragma unroll
    for (int i = 0; i < 12; ++i) {
        float a, b; unpk2(a, b, o2[i]);
        op[2 * i] = a * inv; op[2 * i + 1] = b * inv;
    }
}

// ---------------------------------------------------------------------------
extern "C" void kernel_launch(void* const* d_in, const int* in_sizes, int n_in,
                              void* d_out, int out_size) {
    (void)in_sizes; (void)n_in; (void)out_size;
    const float* x       = (const float*)d_in[0];
    const float* norm1_g = (const float*)d_in[2];
    const float* norm1_b = (const float*)d_in[3];
    const float* qkv_w   = (const float*)d_in[4];
    const float* qkv_b   = (const float*)d_in[5];
    const float* proj_w  = (const float*)d_in[6];
    const float* proj_b  = (const float*)d_in[7];
    const float* norm2_g = (const float*)d_in[8];
    const float* norm2_b = (const float*)d_in[9];
    const float* fc1_w   = (const float*)d_in[10];
    const float* fc1_b   = (const float*)d_in[11];
    const float* fc2_w   = (const float*)d_in[12];
    const float* fc2_b   = (const float*)d_in[13];
    float* out = (float*)d_out;

    float *xw, *qkv, *attn, *x2, *xn2, *hbuf;
    cudaGetSymbolAddress((void**)&xw,   g_xw);
    cudaGetSymbolAddress((void**)&qkv,  g_qkv);
    cudaGetSymbolAddress((void**)&attn, g_attn);
    cudaGetSymbolAddress((void**)&x2,   g_x2);
    cudaGetSymbolAddress((void**)&xn2,  g_xn2);
    cudaGetSymbolAddress((void**)&hbuf, g_h);

    const int gsmem = 2 * (BMX + BNX) * STR * 4;  // 64512 B
    cudaFuncSetAttribute(gemm_pipe<EPI_QKV >, cudaFuncAttributeMaxDynamicSharedMemorySize, gsmem);
    cudaFuncSetAttribute(gemm_pipe<EPI_PROJ>, cudaFuncAttributeMaxDynamicSharedMemorySize, gsmem);
    cudaFuncSetAttribute(gemm_pipe<EPI_FC1 >, cudaFuncAttributeMaxDynamicSharedMemorySize, gsmem);
    cudaFuncSetAttribute(gemm_pipe<EPI_FC2 >, cudaFuncAttributeMaxDynamicSharedMemorySize, gsmem);

    const int attn_smem = (2 * NTOK * HD) * 4 + 256;
    cudaFuncSetAttribute(attn_kernel, cudaFuncAttributeMaxDynamicSharedMemorySize, attn_smem);

    ln_kernel<<<TOKENS / 8, 256>>>(x, norm1_g, norm1_b, xw, 1);
    gemm_pipe<EPI_QKV><<<dim3(TOKENS / BMX, 3), 256, gsmem>>>(xw, CDIM, qkv_w, qkv_b, nullptr, qkv);
    attn_kernel<<<dim3(NWIN, NHEADS), 256, attn_smem>>>(qkv, attn);
    gemm_pipe<EPI_PROJ><<<dim3(TOKENS / BMX, 1), 256, gsmem>>>(attn, CDIM, proj_w, proj_b, x, x2);
    ln_kernel<<<TOKENS / 8, 256>>>(x2, norm2_g, norm2_b, xn2, 0);
    gemm_pipe<EPI_FC1><<<dim3(TOKENS / BMX, HIDDEN_DIM / BNX), 256, gsmem>>>(xn2, CDIM, fc1_w, fc1_b, nullptr, hbuf);
    gemm_pipe<EPI_FC2><<<dim3(TOKENS / BMX, 1), 256, gsmem>>>(hbuf, HIDDEN_DIM, fc2_w, fc2_b, x2, out);
}